// round 12
// baseline (speedup 1.0000x reference)
#include <cuda_runtime.h>
#include <cuda_bf16.h>

typedef unsigned long long ull;

#define B_SZ 64
#define T_SZ 2048
#define HID  256
#define VOC  512
#define DEP  128
#define VD   8
#define MROWS (B_SZ * T_SZ)

__device__ float g_pre[(size_t)MROWS * HID];
__device__ float g_hid[(size_t)MROWS * HID];

__device__ __forceinline__ ull ffma2(ull a, ull b, ull c) {
    ull d;
    asm("fma.rn.f32x2 %0, %1, %2, %3;" : "=l"(d) : "l"(a), "l"(b), "l"(c));
    return d;
}
__device__ __forceinline__ ull dup2(float x) {
    ull d;
    asm("mov.b64 %0, {%1, %1};" : "=l"(d) : "f"(x));
    return d;
}
__device__ __forceinline__ void unpack2(ull v, float& lo, float& hi) {
    asm("mov.b64 {%0, %1}, %2;" : "=f"(lo), "=f"(hi) : "l"(v));
}

// ---------------------------------------------------------------------------
// GEMM v2 (measured 628us): C[M,N] = A[M,K] @ B[N,K]^T (+bias1+bias2).
// 128x128 tile, BK=16, 256 threads, 4(tx)x8(ty) warp footprint, 4+4 split.
// ---------------------------------------------------------------------------
__global__ __launch_bounds__(256) void k_gemm(
    const float* __restrict__ A, const float* __restrict__ B,
    const float* __restrict__ bias1, const float* __restrict__ bias2,
    float* __restrict__ C, int N, int K)
{
    __shared__ float As[16 * 132];
    __shared__ float Bs[16 * 132];

    const int tid = threadIdx.x;
    const int w = tid >> 5, l = tid & 31;
    const int tx = ((w & 3) << 2) | (l >> 3);
    const int ty = ((w >> 2) << 3) | (l & 7);
    const int m0 = blockIdx.y << 7, n0 = blockIdx.x << 7;
    const int r0 = tid >> 2;
    const int kq = (tid & 3) << 2;

    const float* Ap0 = A + (size_t)(m0 + r0) * K + kq;
    const float* Ap1 = Ap0 + (size_t)64 * K;
    const float* Bp0 = B + (size_t)(n0 + r0) * K + kq;
    const float* Bp1 = Bp0 + (size_t)64 * K;

    ull acc[8][4];
#pragma unroll
    for (int i = 0; i < 8; i++)
#pragma unroll
        for (int p = 0; p < 4; p++) acc[i][p] = 0ull;

    float4 a0v = *(const float4*)Ap0;
    float4 a1v = *(const float4*)Ap1;
    float4 b0v = *(const float4*)Bp0;
    float4 b1v = *(const float4*)Bp1;

    const int ktiles = K >> 4;
    for (int t = 0; t < ktiles; t++) {
        As[(kq + 0) * 132 + r0] = a0v.x; As[(kq + 1) * 132 + r0] = a0v.y;
        As[(kq + 2) * 132 + r0] = a0v.z; As[(kq + 3) * 132 + r0] = a0v.w;
        As[(kq + 0) * 132 + r0 + 64] = a1v.x; As[(kq + 1) * 132 + r0 + 64] = a1v.y;
        As[(kq + 2) * 132 + r0 + 64] = a1v.z; As[(kq + 3) * 132 + r0 + 64] = a1v.w;
        Bs[(kq + 0) * 132 + r0] = b0v.x; Bs[(kq + 1) * 132 + r0] = b0v.y;
        Bs[(kq + 2) * 132 + r0] = b0v.z; Bs[(kq + 3) * 132 + r0] = b0v.w;
        Bs[(kq + 0) * 132 + r0 + 64] = b1v.x; Bs[(kq + 1) * 132 + r0 + 64] = b1v.y;
        Bs[(kq + 2) * 132 + r0 + 64] = b1v.z; Bs[(kq + 3) * 132 + r0 + 64] = b1v.w;
        __syncthreads();

        if (t + 1 < ktiles) {
            Ap0 += 16; Ap1 += 16; Bp0 += 16; Bp1 += 16;
            a0v = *(const float4*)Ap0; a1v = *(const float4*)Ap1;
            b0v = *(const float4*)Bp0; b1v = *(const float4*)Bp1;
        }

#pragma unroll
        for (int k = 0; k < 16; k++) {
            float4 af0 = *(const float4*)&As[k * 132 + ty * 4];
            float4 af1 = *(const float4*)&As[k * 132 + 64 + ty * 4];
            float4 bf0 = *(const float4*)&Bs[k * 132 + tx * 4];
            float4 bf1 = *(const float4*)&Bs[k * 132 + 64 + tx * 4];
            ull bl0 = ((ull*)&bf0)[0], bl1 = ((ull*)&bf0)[1];
            ull bl2 = ((ull*)&bf1)[0], bl3 = ((ull*)&bf1)[1];
            float am[8] = {af0.x, af0.y, af0.z, af0.w, af1.x, af1.y, af1.z, af1.w};
#pragma unroll
            for (int i = 0; i < 8; i++) {
                ull ad = dup2(am[i]);
                acc[i][0] = ffma2(ad, bl0, acc[i][0]);
                acc[i][1] = ffma2(ad, bl1, acc[i][1]);
                acc[i][2] = ffma2(ad, bl2, acc[i][2]);
                acc[i][3] = ffma2(ad, bl3, acc[i][3]);
            }
        }
        __syncthreads();
    }

    const int mA = m0 + ty * 4;
    const int nA = n0 + tx * 4;
    float bb[8];
#pragma unroll
    for (int q = 0; q < 8; q++) {
        int col = (q < 4) ? (nA + q) : (nA + 64 + q - 4);
        bb[q] = 0.0f;
        if (bias1) bb[q] += bias1[col];
        if (bias2) bb[q] += bias2[col];
    }
#pragma unroll
    for (int i = 0; i < 8; i++) {
        int row = (i < 4) ? (mA + i) : (mA + 64 + i - 4);
        float r[8];
#pragma unroll
        for (int p = 0; p < 4; p++) unpack2(acc[i][p], r[2 * p], r[2 * p + 1]);
#pragma unroll
        for (int q = 0; q < 8; q++) r[q] += bb[q];
        *(float4*)&C[(size_t)row * N + nA]      = make_float4(r[0], r[1], r[2], r[3]);
        *(float4*)&C[(size_t)row * N + nA + 64] = make_float4(r[4], r[5], r[6], r[7]);
    }
}

// ---------------------------------------------------------------------------
// Scan v5 = v4 + padded h-tilde array (fixes the 2-way broadcast bank
// conflict: the two per-warp broadcast addresses now differ by 528B = 4
// banks instead of 512B = 0 banks). 512 threads, 2 threads/row (k-split),
// 36 u64 register weights + 14 LDS.128 smem weights per thread.
// ---------------------------------------------------------------------------
#define SM_WS  0                        // 512*60
#define SM_HT  (512 * 60)               // 264: k at [k + 4*(k>=128)]
#define SM_HN  (SM_HT + 264)            // 256
#define SM_WG  (SM_HN + 256)            // 11*256
#define SM_GA  (SM_WG + 11 * 256)       // 4
#define SM_GN  (SM_GA + 4)              // 8 (+pad)
#define SM_STK (SM_GN + 12)             // 2*1024 (16B aligned)
#define SM_FLOATS (SM_STK + 2048)

__global__ __launch_bounds__(512, 1) void k_scan(
    const float* __restrict__ W_hh, const float* __restrict__ W_sh,
    const float* __restrict__ W_a,  const float* __restrict__ W_n,
    const float* __restrict__ stack0, const float* __restrict__ hidden0,
    float* __restrict__ out_stack, float* __restrict__ out_hidden)
{
    extern __shared__ float sm[];
    const int b    = blockIdx.x;
    const int tid  = threadIdx.x;
    const int row  = tid >> 1;      // 0..255 hidden unit
    const int half = tid & 1;       // k-range [half*128, half*128+128)
    const int wrp  = tid >> 5, ln = tid & 31;

    // W_hh[row][half*128 + (0..71)] -> 36 u64 regs; (72..127) -> smem (stride 60)
    ull w2[36];
    const float* wr = W_hh + row * 256 + half * 128;
#pragma unroll
    for (int i = 0; i < 36; i++) w2[i] = ((const ull*)wr)[i];
#pragma unroll
    for (int j = 0; j < 14; j++)
        ((float4*)(sm + SM_WS + tid * 60))[j] = ((const float4*)(wr + 72))[j];

    for (int i = tid; i < 11 * 256; i += 512) {
        int j = i >> 8, k = i & 255;
        sm[SM_WG + i] = (j < 3) ? W_a[j * 256 + k] : W_n[(j - 3) * 256 + k];
    }
    float wsh[8];
#pragma unroll
    for (int v = 0; v < 8; v++) wsh[v] = (half == 0) ? W_sh[row * 8 + v] : 0.0f;
    for (int i = tid; i < 1024; i += 512) sm[SM_STK + i] = stack0[b * 1024 + i];
    float hid = (half == 0) ? hidden0[b * 256 + row] : 0.0f;
    __syncthreads();

    const float* prep = g_pre + (size_t)b * T_SZ * 256 + row;
    float* recp = g_hid + (size_t)b * T_SZ * 256 + row;
    const float4* wsm4 = (const float4*)(sm + SM_WS + tid * 60);
    const int ht_idx = row + ((row >> 7) << 2);   // pad 4 floats between halves
    int cur = 0;
    float pre_next = (half == 0) ? prep[0] : 0.0f;

    for (int t = 0; t < T_SZ; t++) {
        float* S    = sm + SM_STK + cur * 1024;
        float* Snew = sm + SM_STK + (cur ^ 1) * 1024;

        if (half == 0) {
            float htv = hid;
#pragma unroll
            for (int v = 0; v < 8; v++) htv = fmaf(wsh[v], S[v], htv);
            sm[SM_HT + ht_idx] = htv;
        }
        __syncthreads();                          // A: s_ht ready

        float pre_cur = pre_next;
        if (half == 0 && t + 1 < T_SZ) pre_next = prep[(size_t)(t + 1) * 256];

        ull a0 = 0ull, a1 = 0ull, a2 = 0ull, a3 = 0ull;
        const float4* hq4 = (const float4*)(sm + SM_HT) + half * 33;  // 132 floats
#pragma unroll
        for (int i = 0; i < 18; i++) {            // k offsets 0..71 (registers)
            float4 hq = hq4[i];
            if (i & 1) {
                a2 = ffma2(w2[2 * i],     ((ull*)&hq)[0], a2);
                a3 = ffma2(w2[2 * i + 1], ((ull*)&hq)[1], a3);
            } else {
                a0 = ffma2(w2[2 * i],     ((ull*)&hq)[0], a0);
                a1 = ffma2(w2[2 * i + 1], ((ull*)&hq)[1], a1);
            }
        }
#pragma unroll
        for (int i = 0; i < 14; i++) {            // k offsets 72..127 (smem)
            float4 hq = hq4[18 + i];
            float4 wq = wsm4[i];
            if (i & 1) {
                a2 = ffma2(((ull*)&wq)[0], ((ull*)&hq)[0], a2);
                a3 = ffma2(((ull*)&wq)[1], ((ull*)&hq)[1], a3);
            } else {
                a0 = ffma2(((ull*)&wq)[0], ((ull*)&hq)[0], a0);
                a1 = ffma2(((ull*)&wq)[1], ((ull*)&hq)[1], a1);
            }
        }
        float l0, h0, l1, h1, l2, h2, l3, h3;
        unpack2(a0, l0, h0); unpack2(a1, l1, h1);
        unpack2(a2, l2, h2); unpack2(a3, l3, h3);
        float part = ((l0 + l1) + (h0 + h1)) + ((l2 + l3) + (h2 + h3));
        part += __shfl_xor_sync(0xffffffffu, part, 1);   // combine k-halves

        if (half == 0) {
            float hv = tanhf(pre_cur + part);
            hid = hv;
            sm[SM_HN + row] = hv;
            recp[(size_t)t * 256] = hv;
        }
        __syncthreads();                          // B: s_hn ready

        // Gates: warps 0..7 -> n-logit wrp; warp 8 -> 3 a-logits + softmax.
        if (wrp < 8) {
            const float* gwn = sm + SM_WG + (3 + wrp) * 256;
            float pn = 0.0f;
#pragma unroll
            for (int i = 0; i < 8; i++)
                pn = fmaf(sm[SM_HN + ln + 32 * i], gwn[ln + 32 * i], pn);
#pragma unroll
            for (int o = 16; o > 0; o >>= 1)
                pn += __shfl_xor_sync(0xffffffffu, pn, o);
            if (ln == 0) sm[SM_GN + wrp] = 1.0f / (1.0f + expf(-pn));
        } else if (wrp == 8) {
            float p0 = 0.0f, p1 = 0.0f, p2 = 0.0f;
#pragma unroll
            for (int i = 0; i < 8; i++) {
                float hvv = sm[SM_HN + ln + 32 * i];
                p0 = fmaf(hvv, sm[SM_WG + 0 * 256 + ln + 32 * i], p0);
                p1 = fmaf(hvv, sm[SM_WG + 1 * 256 + ln + 32 * i], p1);
                p2 = fmaf(hvv, sm[SM_WG + 2 * 256 + ln + 32 * i], p2);
            }
#pragma unroll
            for (int o = 16; o > 0; o >>= 1) {
                p0 += __shfl_xor_sync(0xffffffffu, p0, o);
                p1 += __shfl_xor_sync(0xffffffffu, p1, o);
                p2 += __shfl_xor_sync(0xffffffffu, p2, o);
            }
            if (ln == 0) {
                float mx = fmaxf(p0, fmaxf(p1, p2));
                float e0 = expf(p0 - mx), e1 = expf(p1 - mx), e2 = expf(p2 - mx);
                float inv = 1.0f / (e0 + e1 + e2);
                sm[SM_GA + 0] = e0 * inv;
                sm[SM_GA + 1] = e1 * inv;
                sm[SM_GA + 2] = e2 * inv;
            }
        }
        __syncthreads();                          // C: gates ready

        float ga0 = sm[SM_GA + 0], ga1 = sm[SM_GA + 1], ga2 = sm[SM_GA + 2];
#pragma unroll
        for (int e = tid; e < 1024; e += 512) {
            int d = e >> 3, v = e & 7;
            float push = (d == 0)   ? sm[SM_GN + v] : S[e - 8];
            float pop  = (d == 127) ? 0.0f          : S[e + 8];
            Snew[e] = ga0 * push + ga1 * pop + ga2 * S[e];
        }
        cur ^= 1;
        __syncthreads();                          // D: Snew ready
    }

    for (int i = tid; i < 1024; i += 512)
        out_stack[b * 1024 + i] = sm[SM_STK + cur * 1024 + i];
    if (half == 0) out_hidden[b * 256 + row] = hid;
}

extern "C" void kernel_launch(void* const* d_in, const int* in_sizes, int n_in,
                              void* d_out, int out_size)
{
    const float* inputs  = (const float*)d_in[0];
    const float* stack0  = (const float*)d_in[1];
    const float* hidden0 = (const float*)d_in[2];
    const float* W_ih    = (const float*)d_in[3];
    const float* b_ih    = (const float*)d_in[4];
    const float* W_hh    = (const float*)d_in[5];
    const float* b_hh    = (const float*)d_in[6];
    const float* W_sh    = (const float*)d_in[7];
    const float* W_y     = (const float*)d_in[8];
    const float* W_a     = (const float*)d_in[9];
    const float* W_n     = (const float*)d_in[10];
    float* out = (float*)d_out;

    float *pre_p, *hid_p;
    cudaGetSymbolAddress((void**)&pre_p, g_pre);
    cudaGetSymbolAddress((void**)&hid_p, g_hid);

    const size_t OFF_STACK = (size_t)B_SZ * T_SZ * VOC;
    const size_t OFF_HID   = OFF_STACK + (size_t)B_SZ * DEP * VD;

    // pre = inputs @ W_ih^T + b_ih + b_hh
    k_gemm<<<dim3(HID / 128, MROWS / 128), 256>>>(
        inputs, W_ih, b_ih, b_hh, pre_p, HID, VOC);

    // sequential scan
    cudaFuncSetAttribute(k_scan, cudaFuncAttributeMaxDynamicSharedMemorySize,
                         SM_FLOATS * sizeof(float));
    k_scan<<<B_SZ, 512, SM_FLOATS * sizeof(float)>>>(
        W_hh, W_sh, W_a, W_n, stack0, hidden0,
        out + OFF_STACK, out + OFF_HID);

    // outputs = hidden_rec @ W_y^T
    k_gemm<<<dim3(VOC / 128, MROWS / 128), 256>>>(
        hid_p, W_y, nullptr, nullptr, out, VOC, HID);
}

// round 14
// speedup vs baseline: 1.1068x; 1.1068x over previous
#include <cuda_runtime.h>
#include <cuda_bf16.h>

typedef unsigned long long ull;

#define B_SZ 64
#define T_SZ 2048
#define HID  256
#define VOC  512
#define DEP  128
#define VD   8
#define MROWS (B_SZ * T_SZ)

__device__ float g_pre[(size_t)MROWS * HID];
__device__ float g_hid[(size_t)MROWS * HID];

__device__ __forceinline__ ull ffma2(ull a, ull b, ull c) {
    ull d;
    asm("fma.rn.f32x2 %0, %1, %2, %3;" : "=l"(d) : "l"(a), "l"(b), "l"(c));
    return d;
}
__device__ __forceinline__ ull dup2(float x) {
    ull d;
    asm("mov.b64 %0, {%1, %1};" : "=l"(d) : "f"(x));
    return d;
}
__device__ __forceinline__ void unpack2(ull v, float& lo, float& hi) {
    asm("mov.b64 {%0, %1}, %2;" : "=f"(lo), "=f"(hi) : "l"(v));
}

// ---------------------------------------------------------------------------
// GEMM v2 (measured 628us): C[M,N] = A[M,K] @ B[N,K]^T (+bias1+bias2).
// 128x128 tile, BK=16, 256 threads, 4(tx)x8(ty) warp footprint, 4+4 split.
// ---------------------------------------------------------------------------
__global__ __launch_bounds__(256) void k_gemm(
    const float* __restrict__ A, const float* __restrict__ B,
    const float* __restrict__ bias1, const float* __restrict__ bias2,
    float* __restrict__ C, int N, int K)
{
    __shared__ float As[16 * 132];
    __shared__ float Bs[16 * 132];

    const int tid = threadIdx.x;
    const int w = tid >> 5, l = tid & 31;
    const int tx = ((w & 3) << 2) | (l >> 3);
    const int ty = ((w >> 2) << 3) | (l & 7);
    const int m0 = blockIdx.y << 7, n0 = blockIdx.x << 7;
    const int r0 = tid >> 2;
    const int kq = (tid & 3) << 2;

    const float* Ap0 = A + (size_t)(m0 + r0) * K + kq;
    const float* Ap1 = Ap0 + (size_t)64 * K;
    const float* Bp0 = B + (size_t)(n0 + r0) * K + kq;
    const float* Bp1 = Bp0 + (size_t)64 * K;

    ull acc[8][4];
#pragma unroll
    for (int i = 0; i < 8; i++)
#pragma unroll
        for (int p = 0; p < 4; p++) acc[i][p] = 0ull;

    float4 a0v = *(const float4*)Ap0;
    float4 a1v = *(const float4*)Ap1;
    float4 b0v = *(const float4*)Bp0;
    float4 b1v = *(const float4*)Bp1;

    const int ktiles = K >> 4;
    for (int t = 0; t < ktiles; t++) {
        As[(kq + 0) * 132 + r0] = a0v.x; As[(kq + 1) * 132 + r0] = a0v.y;
        As[(kq + 2) * 132 + r0] = a0v.z; As[(kq + 3) * 132 + r0] = a0v.w;
        As[(kq + 0) * 132 + r0 + 64] = a1v.x; As[(kq + 1) * 132 + r0 + 64] = a1v.y;
        As[(kq + 2) * 132 + r0 + 64] = a1v.z; As[(kq + 3) * 132 + r0 + 64] = a1v.w;
        Bs[(kq + 0) * 132 + r0] = b0v.x; Bs[(kq + 1) * 132 + r0] = b0v.y;
        Bs[(kq + 2) * 132 + r0] = b0v.z; Bs[(kq + 3) * 132 + r0] = b0v.w;
        Bs[(kq + 0) * 132 + r0 + 64] = b1v.x; Bs[(kq + 1) * 132 + r0 + 64] = b1v.y;
        Bs[(kq + 2) * 132 + r0 + 64] = b1v.z; Bs[(kq + 3) * 132 + r0 + 64] = b1v.w;
        __syncthreads();

        if (t + 1 < ktiles) {
            Ap0 += 16; Ap1 += 16; Bp0 += 16; Bp1 += 16;
            a0v = *(const float4*)Ap0; a1v = *(const float4*)Ap1;
            b0v = *(const float4*)Bp0; b1v = *(const float4*)Bp1;
        }

#pragma unroll
        for (int k = 0; k < 16; k++) {
            float4 af0 = *(const float4*)&As[k * 132 + ty * 4];
            float4 af1 = *(const float4*)&As[k * 132 + 64 + ty * 4];
            float4 bf0 = *(const float4*)&Bs[k * 132 + tx * 4];
            float4 bf1 = *(const float4*)&Bs[k * 132 + 64 + tx * 4];
            ull bl0 = ((ull*)&bf0)[0], bl1 = ((ull*)&bf0)[1];
            ull bl2 = ((ull*)&bf1)[0], bl3 = ((ull*)&bf1)[1];
            float am[8] = {af0.x, af0.y, af0.z, af0.w, af1.x, af1.y, af1.z, af1.w};
#pragma unroll
            for (int i = 0; i < 8; i++) {
                ull ad = dup2(am[i]);
                acc[i][0] = ffma2(ad, bl0, acc[i][0]);
                acc[i][1] = ffma2(ad, bl1, acc[i][1]);
                acc[i][2] = ffma2(ad, bl2, acc[i][2]);
                acc[i][3] = ffma2(ad, bl3, acc[i][3]);
            }
        }
        __syncthreads();
    }

    const int mA = m0 + ty * 4;
    const int nA = n0 + tx * 4;
    float bb[8];
#pragma unroll
    for (int q = 0; q < 8; q++) {
        int col = (q < 4) ? (nA + q) : (nA + 64 + q - 4);
        bb[q] = 0.0f;
        if (bias1) bb[q] += bias1[col];
        if (bias2) bb[q] += bias2[col];
    }
#pragma unroll
    for (int i = 0; i < 8; i++) {
        int row = (i < 4) ? (mA + i) : (mA + 64 + i - 4);
        float r[8];
#pragma unroll
        for (int p = 0; p < 4; p++) unpack2(acc[i][p], r[2 * p], r[2 * p + 1]);
#pragma unroll
        for (int q = 0; q < 8; q++) r[q] += bb[q];
        *(float4*)&C[(size_t)row * N + nA]      = make_float4(r[0], r[1], r[2], r[3]);
        *(float4*)&C[(size_t)row * N + nA + 64] = make_float4(r[4], r[5], r[6], r[7]);
    }
}

// ---------------------------------------------------------------------------
// Scan v6 = v3 + h-tilde folded: hidden_new = tanh(pre + W_hh@h + M@top)
// where M = W_hh @ W_sh is computed in the prologue. 3 barriers/step.
// 256 threads, W_hh row: k 0..199 in 100 u64 regs, k 200..255 in smem.
// Double-buffered s_hn (read h_{t-1}, write h_t).
// ---------------------------------------------------------------------------
#define SM_WS  0                        // 256*60 = 15360
#define SM_HN  (256 * 60)               // 2*256 (double buffer)
#define SM_WG  (SM_HN + 512)            // 11*256
#define SM_GA  (SM_WG + 11 * 256)       // 4
#define SM_GN  (SM_GA + 4)              // 8 (+pad)
#define SM_STK (SM_GN + 12)             // 2*1024 (16B aligned)
#define SM_FLOATS (SM_STK + 2048)

__global__ __launch_bounds__(256, 1) void k_scan(
    const float* __restrict__ W_hh, const float* __restrict__ W_sh,
    const float* __restrict__ W_a,  const float* __restrict__ W_n,
    const float* __restrict__ stack0, const float* __restrict__ hidden0,
    float* __restrict__ out_stack, float* __restrict__ out_hidden)
{
    extern __shared__ float sm[];
    const int b = blockIdx.x;
    const int h = threadIdx.x;
    const int wrp = h >> 5, ln = h & 31;

    // W_hh row h: k 0..199 -> 100 u64 regs; k 200..255 -> smem (stride 60)
    ull w2[100];
    const float* wr = W_hh + h * 256;
#pragma unroll
    for (int i = 0; i < 100; i++) w2[i] = ((const ull*)wr)[i];
#pragma unroll
    for (int j = 0; j < 14; j++)
        ((float4*)(sm + SM_WS + h * 60))[j] = ((const float4*)(wr + 200))[j];

    // Stage W_sh (256x8) in the stack area, compute m[v] = (W_hh @ W_sh)[h][v]
    for (int i = h; i < 2048; i += 256) sm[SM_STK + i] = W_sh[i];
    __syncthreads();
    float m[8];
#pragma unroll
    for (int v = 0; v < 8; v++) m[v] = 0.0f;
    {
        const float* ws = sm + SM_STK;
#pragma unroll 4
        for (int i = 0; i < 100; i++) {
            float f0, f1;
            unpack2(w2[i], f0, f1);
            const float* p0 = ws + (2 * i) * 8;
#pragma unroll
            for (int v = 0; v < 8; v++)
                m[v] = fmaf(f0, p0[v], fmaf(f1, p0[8 + v], m[v]));
        }
        const float* wtail = sm + SM_WS + h * 60;
#pragma unroll
        for (int j = 0; j < 56; j++) {
            float fw = wtail[j];
            const float* pv = ws + (200 + j) * 8;
#pragma unroll
            for (int v = 0; v < 8; v++) m[v] = fmaf(fw, pv[v], m[v]);
        }
    }
    __syncthreads();

    for (int i = h; i < 11 * 256; i += 256) {
        int j = i >> 8, k = i & 255;
        sm[SM_WG + i] = (j < 3) ? W_a[j * 256 + k] : W_n[(j - 3) * 256 + k];
    }
    for (int i = h; i < 1024; i += 256) sm[SM_STK + i] = stack0[b * 1024 + i];
    float hid = hidden0[b * 256 + h];
    sm[SM_HN + h] = hid;                 // buffer 0 = h_{-1}
    __syncthreads();

    const float* prep = g_pre + (size_t)b * T_SZ * 256 + h;
    float* recp = g_hid + (size_t)b * T_SZ * 256 + h;
    const float4* wsm4 = (const float4*)(sm + SM_WS + h * 60);
    int cur = 0;
    float pre_next = prep[0];

    for (int t = 0; t < T_SZ; t++) {
        float* S    = sm + SM_STK + cur * 1024;
        float* Snew = sm + SM_STK + (cur ^ 1) * 1024;
        const float* hn_old = sm + SM_HN + cur * 256;
        float* hn_new = sm + SM_HN + (cur ^ 1) * 256;

        float acc = pre_next;
        if (t + 1 < T_SZ) pre_next = prep[(size_t)(t + 1) * 256];

        // M @ stack_top (8 broadcast LDS)
#pragma unroll
        for (int v = 0; v < 8; v++) acc = fmaf(m[v], S[v], acc);

        // W_hh @ h_{t-1}
        ull a2 = 0ull, a2b = 0ull;
        const float4* hq4 = (const float4*)hn_old;
#pragma unroll
        for (int i = 0; i < 25; i++) {           // k 0..199 from registers
            float4 hq0 = hq4[2 * i];
            float4 hq1 = hq4[2 * i + 1];
            a2  = ffma2(w2[4 * i + 0], ((ull*)&hq0)[0], a2);
            a2b = ffma2(w2[4 * i + 1], ((ull*)&hq0)[1], a2b);
            a2  = ffma2(w2[4 * i + 2], ((ull*)&hq1)[0], a2);
            a2b = ffma2(w2[4 * i + 3], ((ull*)&hq1)[1], a2b);
        }
#pragma unroll
        for (int i = 0; i < 7; i++) {            // k 200..255 from smem
            float4 hq0 = hq4[50 + 2 * i];
            float4 hq1 = hq4[51 + 2 * i];
            float4 wq0 = wsm4[2 * i];
            float4 wq1 = wsm4[2 * i + 1];
            a2  = ffma2(((ull*)&wq0)[0], ((ull*)&hq0)[0], a2);
            a2b = ffma2(((ull*)&wq0)[1], ((ull*)&hq0)[1], a2b);
            a2  = ffma2(((ull*)&wq1)[0], ((ull*)&hq1)[0], a2);
            a2b = ffma2(((ull*)&wq1)[1], ((ull*)&hq1)[1], a2b);
        }
        float l0, h0, l1, h1;
        unpack2(a2, l0, h0); unpack2(a2b, l1, h1);
        acc += (l0 + l1) + (h0 + h1);

        float hv = tanhf(acc);
        hid = hv;
        hn_new[h] = hv;
        recp[(size_t)t * 256] = hv;
        __syncthreads();                         // 1: hn_new ready

        // Gates: warp w -> n-logit w; warp 0 also 3 a-logits + softmax.
        {
            const float* gwn = sm + SM_WG + (3 + wrp) * 256;
            float pn = 0.0f, p0 = 0.0f, p1 = 0.0f, p2 = 0.0f;
#pragma unroll
            for (int i = 0; i < 8; i++) {
                float hvv = hn_new[ln + 32 * i];
                pn = fmaf(hvv, gwn[ln + 32 * i], pn);
                if (wrp == 0) {
                    p0 = fmaf(hvv, sm[SM_WG + 0 * 256 + ln + 32 * i], p0);
                    p1 = fmaf(hvv, sm[SM_WG + 1 * 256 + ln + 32 * i], p1);
                    p2 = fmaf(hvv, sm[SM_WG + 2 * 256 + ln + 32 * i], p2);
                }
            }
#pragma unroll
            for (int o = 16; o > 0; o >>= 1)
                pn += __shfl_xor_sync(0xffffffffu, pn, o);
            if (wrp == 0) {
#pragma unroll
                for (int o = 16; o > 0; o >>= 1) {
                    p0 += __shfl_xor_sync(0xffffffffu, p0, o);
                    p1 += __shfl_xor_sync(0xffffffffu, p1, o);
                    p2 += __shfl_xor_sync(0xffffffffu, p2, o);
                }
            }
            if (ln == 0) {
                sm[SM_GN + wrp] = 1.0f / (1.0f + expf(-pn));
                if (wrp == 0) {
                    float mx = fmaxf(p0, fmaxf(p1, p2));
                    float e0 = expf(p0 - mx), e1 = expf(p1 - mx), e2 = expf(p2 - mx);
                    float inv = 1.0f / (e0 + e1 + e2);
                    sm[SM_GA + 0] = e0 * inv;
                    sm[SM_GA + 1] = e1 * inv;
                    sm[SM_GA + 2] = e2 * inv;
                }
            }
        }
        __syncthreads();                         // 2: gates ready

        float a0 = sm[SM_GA + 0], a1 = sm[SM_GA + 1], av2 = sm[SM_GA + 2];
#pragma unroll
        for (int e = h; e < 1024; e += 256) {
            int d = e >> 3, v = e & 7;
            float push = (d == 0)   ? sm[SM_GN + v] : S[e - 8];
            float pop  = (d == 127) ? 0.0f          : S[e + 8];
            Snew[e] = a0 * push + a1 * pop + av2 * S[e];
        }
        cur ^= 1;
        __syncthreads();                         // 3: Snew + hn visible
    }

    for (int i = h; i < 1024; i += 256)
        out_stack[b * 1024 + i] = sm[SM_STK + cur * 1024 + i];
    out_hidden[b * 256 + h] = hid;
}

extern "C" void kernel_launch(void* const* d_in, const int* in_sizes, int n_in,
                              void* d_out, int out_size)
{
    const float* inputs  = (const float*)d_in[0];
    const float* stack0  = (const float*)d_in[1];
    const float* hidden0 = (const float*)d_in[2];
    const float* W_ih    = (const float*)d_in[3];
    const float* b_ih    = (const float*)d_in[4];
    const float* W_hh    = (const float*)d_in[5];
    const float* b_hh    = (const float*)d_in[6];
    const float* W_sh    = (const float*)d_in[7];
    const float* W_y     = (const float*)d_in[8];
    const float* W_a     = (const float*)d_in[9];
    const float* W_n     = (const float*)d_in[10];
    float* out = (float*)d_out;

    float *pre_p, *hid_p;
    cudaGetSymbolAddress((void**)&pre_p, g_pre);
    cudaGetSymbolAddress((void**)&hid_p, g_hid);

    const size_t OFF_STACK = (size_t)B_SZ * T_SZ * VOC;
    const size_t OFF_HID   = OFF_STACK + (size_t)B_SZ * DEP * VD;

    // pre = inputs @ W_ih^T + b_ih + b_hh
    k_gemm<<<dim3(HID / 128, MROWS / 128), 256>>>(
        inputs, W_ih, b_ih, b_hh, pre_p, HID, VOC);

    // sequential scan
    cudaFuncSetAttribute(k_scan, cudaFuncAttributeMaxDynamicSharedMemorySize,
                         SM_FLOATS * sizeof(float));
    k_scan<<<B_SZ, 256, SM_FLOATS * sizeof(float)>>>(
        W_hh, W_sh, W_a, W_n, stack0, hidden0,
        out + OFF_STACK, out + OFF_HID);

    // outputs = hidden_rec @ W_y^T
    k_gemm<<<dim3(VOC / 128, MROWS / 128), 256>>>(
        hid_p, W_y, nullptr, nullptr, out, VOC, HID);
}